// round 6
// baseline (speedup 1.0000x reference)
#include <cuda_runtime.h>
#include <cuda_bf16.h>
#include <stdint.h>

// Problem constants
#define BQ 2048       // queries (rows)
#define DIM 768       // embedding dim
#define NPAS 16384    // passages (cols)
#define NB32 512      // 32-col partial blocks per row
#define ALPHA_C 2.6f
#define OPT_RANK 1.0f
#define SIGMA_C 1.8f

// Static device scratch (allocation-free)
__device__ __align__(16) __nv_bfloat16 g_qbf[BQ * DIM];
__device__ __align__(16) __nv_bfloat16 g_pbf[NPAS * DIM];
__device__ float g_starget[BQ];
__device__ __align__(16) float g_smax[BQ * NB32];
__device__ __align__(16) float g_ssum[BQ * NB32];
__device__ __align__(16) int   g_cnt[BQ * NB32];
__device__ float g_part[256];
__device__ unsigned int g_tick = 0;

// ---------------------------------------------------------------------------
// PTX helpers (plain sm_80+ PTX only; tcgen05 is ptxas-blocked on this build)
// ---------------------------------------------------------------------------
__device__ __forceinline__ uint32_t smem_u32(const void* p) {
    uint32_t a;
    asm("{ .reg .u64 t; cvta.to.shared.u64 t, %1; cvt.u32.u64 %0, t; }"
        : "=r"(a) : "l"(p));
    return a;
}
__device__ __forceinline__ void cp16(uint32_t dst, const void* src) {
    asm volatile("cp.async.cg.shared.global [%0], [%1], 16;"
                 :: "r"(dst), "l"(src) : "memory");
}
#define CP_COMMIT() asm volatile("cp.async.commit_group;" ::: "memory")
#define CP_WAIT2()  asm volatile("cp.async.wait_group 2;" ::: "memory")
#define CP_WAIT1()  asm volatile("cp.async.wait_group 1;" ::: "memory")
#define CP_WAIT0()  asm volatile("cp.async.wait_group 0;" ::: "memory")

#define LDSM4(r0, r1, r2, r3, addr) \
    asm volatile("ldmatrix.sync.aligned.m8n8.x4.shared.b16 {%0,%1,%2,%3}, [%4];" \
                 : "=r"(r0), "=r"(r1), "=r"(r2), "=r"(r3) : "r"(addr))

#define MMA16816(c, a0, a1, a2, a3, b0, b1) \
    asm volatile("mma.sync.aligned.m16n8k16.row.col.f32.bf16.bf16.f32 " \
                 "{%0,%1,%2,%3}, {%4,%5,%6,%7}, {%8,%9}, {%0,%1,%2,%3};" \
                 : "+f"((c)[0]), "+f"((c)[1]), "+f"((c)[2]), "+f"((c)[3]) \
                 : "r"(a0), "r"(a1), "r"(a2), "r"(a3), "r"(b0), "r"(b1))

// MUFU-free e^x for x <= 0 (FMA-pipe only; rel err < 3e-6)
__device__ __forceinline__ float fexp(float x) {
    float t = x * 1.44269504088896f;               // log2(e) * x
    float z = t + 12582912.0f;                     // 2^23 * 1.5 magic (RN)
    int   n = __float_as_int(z) - 0x4B400000;      // nearest int
    float f = t - (float)n;                        // f in [-0.5, 0.5]
    float r = 0.0013333558f;                       // 2^f Taylor (ln2^k/k!)
    r = fmaf(r, f, 0.0096181291f);
    r = fmaf(r, f, 0.0555041087f);
    r = fmaf(r, f, 0.2402265070f);
    r = fmaf(r, f, 0.6931471806f);
    r = fmaf(r, f, 1.0f);
    r = __int_as_float(__float_as_int(r) + (n << 23));
    return (x > -87.0f) ? r : 0.0f;                // avoid exponent wrap
}

// ---------------------------------------------------------------------------
// Kernels 0a/0b: fp32 -> bf16 conversion (8 elems / thread), q and p split
// (split keeps score_kernel in the ncu capture slot)
// ---------------------------------------------------------------------------
__global__ void convert_q_kernel(const float* __restrict__ q) {
    size_t i = ((size_t)blockIdx.x * blockDim.x + threadIdx.x) * 8;
    float4 a = *(const float4*)(q + i);
    float4 b = *(const float4*)(q + i + 4);
    __nv_bfloat162 v0 = __floats2bfloat162_rn(a.x, a.y);
    __nv_bfloat162 v1 = __floats2bfloat162_rn(a.z, a.w);
    __nv_bfloat162 v2 = __floats2bfloat162_rn(b.x, b.y);
    __nv_bfloat162 v3 = __floats2bfloat162_rn(b.z, b.w);
    uint4 u;
    u.x = *(uint32_t*)&v0; u.y = *(uint32_t*)&v1;
    u.z = *(uint32_t*)&v2; u.w = *(uint32_t*)&v3;
    *(uint4*)(g_qbf + i) = u;
}
__global__ void convert_p_kernel(const float* __restrict__ p) {
    size_t i = ((size_t)blockIdx.x * blockDim.x + threadIdx.x) * 8;
    float4 a = *(const float4*)(p + i);
    float4 b = *(const float4*)(p + i + 4);
    __nv_bfloat162 v0 = __floats2bfloat162_rn(a.x, a.y);
    __nv_bfloat162 v1 = __floats2bfloat162_rn(a.z, a.w);
    __nv_bfloat162 v2 = __floats2bfloat162_rn(b.x, b.y);
    __nv_bfloat162 v3 = __floats2bfloat162_rn(b.z, b.w);
    uint4 u;
    u.x = *(uint32_t*)&v0; u.y = *(uint32_t*)&v1;
    u.z = *(uint32_t*)&v2; u.w = *(uint32_t*)&v3;
    *(uint4*)(g_pbf + i) = u;
}

// ---------------------------------------------------------------------------
// Kernel 1: exact fp32 s_target[i] = dot(q[i], p[8i])   (one warp per row)
// ---------------------------------------------------------------------------
__global__ void target_kernel(const float* __restrict__ q,
                              const float* __restrict__ p) {
    int w = (blockIdx.x * blockDim.x + threadIdx.x) >> 5;
    int lane = threadIdx.x & 31;
    if (w >= BQ) return;
    const float* qr = q + (size_t)w * DIM;
    const float* pr = p + (size_t)(w * 8) * DIM;
    float s = 0.f;
    #pragma unroll 4
    for (int k = lane; k < DIM; k += 32) s = fmaf(qr[k], pr[k], s);
    #pragma unroll
    for (int o = 16; o > 0; o >>= 1) s += __shfl_down_sync(0xffffffffu, s, o);
    if (lane == 0) g_starget[w] = s;
}

// ---------------------------------------------------------------------------
// Kernel 2: 128x128 score tile per CTA via mma.sync bf16 (HMMA path).
// Epilogue: per-(row, 32col) block max, poly-exp partial sum, rank counts.
// grid = (128, 16), 256 threads, 4-stage cp.async pipeline.
// ---------------------------------------------------------------------------
#define STG_B 20480u
#define NSTG 4
#define SMEM_BYTES (NSTG * STG_B)
#define NCHUNK 24     // 768 / 32

__global__ __launch_bounds__(256, 2)
void score_kernel() {
    extern __shared__ char smem[];
    const uint32_t sbase = smem_u32(smem);
    const int tid = threadIdx.x;
    const int lane = tid & 31;
    const int wid = tid >> 5;
    const int warpM = wid & 1;      // 2 warps along M (64 rows each)
    const int warpN = wid >> 1;     // 4 warps along N (32 cols each)
    const int cb = blockIdx.x;      // column block 0..127
    const int rb = blockIdx.y;      // row block 0..15

    const __nv_bfloat16* qB = g_qbf + (size_t)(rb * 128) * DIM;
    const __nv_bfloat16* pB = g_pbf + (size_t)(cb * 128) * DIM;

    float acc[4][4][4];
    #pragma unroll
    for (int mi = 0; mi < 4; mi++)
        #pragma unroll
        for (int ni = 0; ni < 4; ni++)
            #pragma unroll
            for (int r = 0; r < 4; r++) acc[mi][ni][r] = 0.f;

    // loader: 1024 x 16B transfers per stage (A 512, B 512), 4 per thread
    auto load_chunk = [&](int stg, int kt) {
        uint32_t base = sbase + (uint32_t)stg * STG_B;
        #pragma unroll
        for (int i = 0; i < 4; i++) {
            int c = tid + (i << 8);
            int isB = (c >= 512);
            int cc = c & 511;
            int row = cc >> 2, seg = cc & 3;
            const __nv_bfloat16* gp = (isB ? pB : qB) + (size_t)row * DIM + kt + seg * 8;
            uint32_t d = base + (isB ? 10240u : 0u) + (uint32_t)row * 80u + ((uint32_t)seg << 4);
            cp16(d, gp);
        }
        CP_COMMIT();
    };

    auto compute_chunk = [&](int stg) {
        uint32_t aB = sbase + (uint32_t)stg * STG_B;
        uint32_t bB = aB + 10240u;
        #pragma unroll
        for (int ks = 0; ks < 2; ks++) {
            uint32_t af_[4][4];
            #pragma unroll
            for (int mi = 0; mi < 4; mi++) {
                uint32_t addr = aB
                    + (uint32_t)((warpM * 64 + mi * 16 + (lane & 15)) * 80)
                    + (uint32_t)(ks * 32 + ((lane >> 4) << 4));
                LDSM4(af_[mi][0], af_[mi][1], af_[mi][2], af_[mi][3], addr);
            }
            uint32_t bf_[2][4];
            #pragma unroll
            for (int nj = 0; nj < 2; nj++) {
                uint32_t addr = bB
                    + (uint32_t)((warpN * 32 + nj * 16 + (lane & 7) + ((lane >> 4) << 3)) * 80)
                    + (uint32_t)(ks * 32 + (((lane >> 3) & 1) << 4));
                LDSM4(bf_[nj][0], bf_[nj][1], bf_[nj][2], bf_[nj][3], addr);
            }
            #pragma unroll
            for (int mi = 0; mi < 4; mi++)
                #pragma unroll
                for (int ni = 0; ni < 4; ni++) {
                    uint32_t b0 = bf_[ni >> 1][(ni & 1) << 1];
                    uint32_t b1 = bf_[ni >> 1][((ni & 1) << 1) + 1];
                    MMA16816(acc[mi][ni], af_[mi][0], af_[mi][1], af_[mi][2], af_[mi][3], b0, b1);
                }
        }
    };

    // 4-stage pipeline over 24 k-chunks
    load_chunk(0, 0);
    load_chunk(1, 32);
    load_chunk(2, 64);
    for (int c = 0; c < NCHUNK; c++) {
        if (c <= NCHUNK - 3)      CP_WAIT2();
        else if (c == NCHUNK - 2) CP_WAIT1();
        else                      CP_WAIT0();
        __syncthreads();
        if (c < NCHUNK - 3) load_chunk((c + 3) & 3, (c + 3) * 32);
        compute_chunk(c & 3);
    }

    // ---- epilogue: block max, poly-exp sum, rank counts ----
    const int g = lane >> 2, q4 = lane & 3;
    #pragma unroll
    for (int mi = 0; mi < 4; mi++) {
        #pragma unroll
        for (int h = 0; h < 2; h++) {
            int row = rb * 128 + warpM * 64 + mi * 16 + h * 8 + g;
            float st = g_starget[row];
            int tcol = row * 8;
            float v[8];
            #pragma unroll
            for (int ni = 0; ni < 4; ni++) {
                v[ni * 2 + 0] = acc[mi][ni][h * 2 + 0];
                v[ni * 2 + 1] = acc[mi][ni][h * 2 + 1];
            }
            float mx = v[0];
            #pragma unroll
            for (int j = 1; j < 8; j++) mx = fmaxf(mx, v[j]);
            int cgt = 0, ceq = 0;
            #pragma unroll
            for (int j = 0; j < 8; j++) {
                int colg = cb * 128 + warpN * 32 + (j >> 1) * 8 + q4 * 2 + (j & 1);
                if (v[j] > st && colg != tcol) cgt++;
                if (v[j] == st && colg < tcol) ceq++;
            }
            int cnt = cgt | (ceq << 16);
            mx = fmaxf(mx, __shfl_xor_sync(0xffffffffu, mx, 1));
            mx = fmaxf(mx, __shfl_xor_sync(0xffffffffu, mx, 2));
            cnt += __shfl_xor_sync(0xffffffffu, cnt, 1);
            cnt += __shfl_xor_sync(0xffffffffu, cnt, 2);
            float s = 0.f;
            #pragma unroll
            for (int j = 0; j < 8; j++) s += fexp(v[j] - mx);
            s += __shfl_xor_sync(0xffffffffu, s, 1);
            s += __shfl_xor_sync(0xffffffffu, s, 2);
            if (q4 == 0) {
                int idx = row * NB32 + cb * 4 + warpN;
                g_smax[idx] = mx;
                g_ssum[idx] = s;
                g_cnt[idx]  = cnt;
            }
        }
    }
}

// ---------------------------------------------------------------------------
// Kernel 3: warp-per-row combine -> per-block partial -> last block writes out.
// grid = 256, block = 256 (8 rows per block).
// ---------------------------------------------------------------------------
__global__ __launch_bounds__(256)
void combine_kernel(float* __restrict__ out) {
    __shared__ float sh[8];
    const int lane = threadIdx.x & 31;
    const int warp = threadIdx.x >> 5;
    const int row = blockIdx.x * 8 + warp;

    const float4* smax4 = (const float4*)(g_smax + (size_t)row * NB32);
    const float4* ssum4 = (const float4*)(g_ssum + (size_t)row * NB32);
    const int4*   cnt4  = (const int4*)  (g_cnt  + (size_t)row * NB32);

    // pass 1: global row max + rank counts
    float mx = -3.0e38f;
    int cnt = 0;
    #pragma unroll
    for (int k = 0; k < 4; k++) {
        float4 m = smax4[k * 32 + lane];
        int4   c = cnt4 [k * 32 + lane];
        mx = fmaxf(fmaxf(fmaxf(mx, m.x), fmaxf(m.y, m.z)), m.w);
        cnt += c.x + c.y + c.z + c.w;
    }
    #pragma unroll
    for (int o = 16; o > 0; o >>= 1) {
        mx = fmaxf(mx, __shfl_xor_sync(0xffffffffu, mx, o));
        cnt += __shfl_xor_sync(0xffffffffu, cnt, o);
    }

    // pass 2: S = sum_b ssum_b * exp(smax_b - M)
    float S = 0.f;
    #pragma unroll
    for (int k = 0; k < 4; k++) {
        float4 m = smax4[k * 32 + lane];
        float4 s = ssum4[k * 32 + lane];
        S += s.x * fexp(m.x - mx) + s.y * fexp(m.y - mx)
           + s.z * fexp(m.z - mx) + s.w * fexp(m.w - mx);
    }
    #pragma unroll
    for (int o = 16; o > 0; o >>= 1) S += __shfl_xor_sync(0xffffffffu, S, o);

    if (lane == 0) {
        float rank = (float)((cnt & 0xffff) + (cnt >> 16));
        float raw = mx + logf(S) - g_starget[row];
        float dr = rank - OPT_RANK;
        float w = 1.0f + ALPHA_C * expf(-(dr * dr) / (2.0f * SIGMA_C * SIGMA_C));
        sh[warp] = raw * w;
    }
    __syncthreads();
    if (threadIdx.x == 0) {
        float t = 0.f;
        #pragma unroll
        for (int i = 0; i < 8; i++) t += sh[i];
        g_part[blockIdx.x] = t;
        __threadfence();
        unsigned int ticket = atomicAdd(&g_tick, 1u);
        if (ticket == 255u) {                  // last block: deterministic sum
            float tot = 0.f;
            for (int i = 0; i < 256; i++) tot += g_part[i];
            out[0] = tot * (1.0f / (float)BQ);
            g_tick = 0u;                       // reset for next replay
        }
    }
}

// ---------------------------------------------------------------------------
extern "C" void kernel_launch(void* const* d_in, const int* in_sizes, int n_in,
                              void* d_out, int out_size) {
    const float* q = (const float*)d_in[0];   // [2048, 768] fp32
    const float* p = (const float*)d_in[1];   // [16384, 768] fp32
    float* out = (float*)d_out;

    cudaFuncSetAttribute(score_kernel,
                         cudaFuncAttributeMaxDynamicSharedMemorySize, SMEM_BYTES);

    convert_q_kernel<<<(BQ * DIM) / 8 / 256, 256>>>(q);     // launch 1
    convert_p_kernel<<<(NPAS * DIM) / 8 / 256, 256>>>(p);   // launch 2
    target_kernel<<<BQ / 8, 256>>>(q, p);                   // launch 3
    dim3 grid(NPAS / 128, BQ / 128);                        // (128, 16)
    score_kernel<<<grid, 256, SMEM_BYTES>>>();              // launch 4 (ncu slot)
    combine_kernel<<<BQ / 8, 256>>>(out);                   // launch 5
}

// round 10
// speedup vs baseline: 1.0917x; 1.0917x over previous
#include <cuda_runtime.h>
#include <cuda_bf16.h>
#include <stdint.h>

// Problem constants
#define BQ 2048       // queries (rows)
#define DIM 768       // embedding dim
#define NPAS 16384    // passages (cols)
#define NB32 512      // 32-col partial blocks per row
#define ALPHA_C 2.6f
#define OPT_RANK 1.0f
#define SIGMA_C 1.8f

// Static device scratch (allocation-free)
__device__ __align__(16) __nv_bfloat16 g_qbf[BQ * DIM];
__device__ __align__(16) __nv_bfloat16 g_pbf[NPAS * DIM];
__device__ float g_starget[BQ];
__device__ __align__(16) float g_smax[BQ * NB32];
__device__ __align__(16) float g_ssum[BQ * NB32];
__device__ __align__(16) int   g_cnt[BQ * NB32];
__device__ float g_part[256];
__device__ unsigned int g_tick = 0;

// ---------------------------------------------------------------------------
// PTX helpers (plain sm_80+ PTX only; tcgen05 is ptxas-blocked on this build)
// ---------------------------------------------------------------------------
__device__ __forceinline__ uint32_t smem_u32(const void* p) {
    uint32_t a;
    asm("{ .reg .u64 t; cvta.to.shared.u64 t, %1; cvt.u32.u64 %0, t; }"
        : "=r"(a) : "l"(p));
    return a;
}
__device__ __forceinline__ void cp16(uint32_t dst, const void* src) {
    asm volatile("cp.async.cg.shared.global [%0], [%1], 16;"
                 :: "r"(dst), "l"(src) : "memory");
}
#define CP_COMMIT() asm volatile("cp.async.commit_group;" ::: "memory")
#define CP_WAIT0()  asm volatile("cp.async.wait_group 0;" ::: "memory")

#define LDSM4(r0, r1, r2, r3, addr) \
    asm volatile("ldmatrix.sync.aligned.m8n8.x4.shared.b16 {%0,%1,%2,%3}, [%4];" \
                 : "=r"(r0), "=r"(r1), "=r"(r2), "=r"(r3) : "r"(addr))

#define MMA16816(c, a0, a1, a2, a3, b0, b1) \
    asm volatile("mma.sync.aligned.m16n8k16.row.col.f32.bf16.bf16.f32 " \
                 "{%0,%1,%2,%3}, {%4,%5,%6,%7}, {%8,%9}, {%0,%1,%2,%3};" \
                 : "+f"((c)[0]), "+f"((c)[1]), "+f"((c)[2]), "+f"((c)[3]) \
                 : "r"(a0), "r"(a1), "r"(a2), "r"(a3), "r"(b0), "r"(b1))

// MUFU-free e^x for x <= 0 (FMA-pipe only; rel err < 3e-6)
__device__ __forceinline__ float fexp(float x) {
    float t = x * 1.44269504088896f;               // log2(e) * x
    float z = t + 12582912.0f;                     // 2^23 * 1.5 magic (RN)
    int   n = __float_as_int(z) - 0x4B400000;      // nearest int
    float f = t - (float)n;                        // f in [-0.5, 0.5]
    float r = 0.0013333558f;                       // 2^f Taylor (ln2^k/k!)
    r = fmaf(r, f, 0.0096181291f);
    r = fmaf(r, f, 0.0555041087f);
    r = fmaf(r, f, 0.2402265070f);
    r = fmaf(r, f, 0.6931471806f);
    r = fmaf(r, f, 1.0f);
    r = __int_as_float(__float_as_int(r) + (n << 23));
    return (x > -87.0f) ? r : 0.0f;                // avoid exponent wrap
}

// ---------------------------------------------------------------------------
// Kernels 0a/0b: fp32 -> bf16 conversion (8 elems / thread), q and p split
// (split keeps score_kernel in the ncu capture slot = launch #4)
// ---------------------------------------------------------------------------
__global__ void convert_q_kernel(const float* __restrict__ q) {
    size_t i = ((size_t)blockIdx.x * blockDim.x + threadIdx.x) * 8;
    float4 a = *(const float4*)(q + i);
    float4 b = *(const float4*)(q + i + 4);
    __nv_bfloat162 v0 = __floats2bfloat162_rn(a.x, a.y);
    __nv_bfloat162 v1 = __floats2bfloat162_rn(a.z, a.w);
    __nv_bfloat162 v2 = __floats2bfloat162_rn(b.x, b.y);
    __nv_bfloat162 v3 = __floats2bfloat162_rn(b.z, b.w);
    uint4 u;
    u.x = *(uint32_t*)&v0; u.y = *(uint32_t*)&v1;
    u.z = *(uint32_t*)&v2; u.w = *(uint32_t*)&v3;
    *(uint4*)(g_qbf + i) = u;
}
__global__ void convert_p_kernel(const float* __restrict__ p) {
    size_t i = ((size_t)blockIdx.x * blockDim.x + threadIdx.x) * 8;
    float4 a = *(const float4*)(p + i);
    float4 b = *(const float4*)(p + i + 4);
    __nv_bfloat162 v0 = __floats2bfloat162_rn(a.x, a.y);
    __nv_bfloat162 v1 = __floats2bfloat162_rn(a.z, a.w);
    __nv_bfloat162 v2 = __floats2bfloat162_rn(b.x, b.y);
    __nv_bfloat162 v3 = __floats2bfloat162_rn(b.z, b.w);
    uint4 u;
    u.x = *(uint32_t*)&v0; u.y = *(uint32_t*)&v1;
    u.z = *(uint32_t*)&v2; u.w = *(uint32_t*)&v3;
    *(uint4*)(g_pbf + i) = u;
}

// ---------------------------------------------------------------------------
// Kernel 1: exact fp32 s_target[i] = dot(q[i], p[8i])   (one warp per row)
// ---------------------------------------------------------------------------
__global__ void target_kernel(const float* __restrict__ q,
                              const float* __restrict__ p) {
    int w = (blockIdx.x * blockDim.x + threadIdx.x) >> 5;
    int lane = threadIdx.x & 31;
    if (w >= BQ) return;
    const float* qr = q + (size_t)w * DIM;
    const float* pr = p + (size_t)(w * 8) * DIM;
    float s = 0.f;
    #pragma unroll 4
    for (int k = lane; k < DIM; k += 32) s = fmaf(qr[k], pr[k], s);
    #pragma unroll
    for (int o = 16; o > 0; o >>= 1) s += __shfl_down_sync(0xffffffffu, s, o);
    if (lane == 0) g_starget[w] = s;
}

// ---------------------------------------------------------------------------
// Kernel 2: 128x128 score tile per CTA via mma.sync bf16 (HMMA path).
// BK=64 chunks, 2-stage cp.async ring -> 12 sync points instead of 24/48.
// Row stride 144B (9 x 16B granules) -> ldmatrix conflict-free (stride odd).
// Epilogue: per-(row, 32col) block max, poly-exp partial sum, rank counts.
// grid = (128, 16), 256 threads.
// ---------------------------------------------------------------------------
#define ROW_B 144u
#define A_BYTES (128u * ROW_B)          // 18432
#define STG_B (2u * A_BYTES)            // 36864 (A + B)
#define NSTG 2
#define SMEM_BYTES (NSTG * STG_B)       // 73728
#define NCH64 12                        // 768 / 64

__global__ __launch_bounds__(256, 2)
void score_kernel() {
    extern __shared__ char smem[];
    const uint32_t sbase = smem_u32(smem);
    const int tid = threadIdx.x;
    const int lane = tid & 31;
    const int wid = tid >> 5;
    const int warpM = wid & 1;      // 2 warps along M (64 rows each)
    const int warpN = wid >> 1;     // 4 warps along N (32 cols each)
    const int cb = blockIdx.x;      // column block 0..127
    const int rb = blockIdx.y;      // row block 0..15

    const __nv_bfloat16* qB = g_qbf + (size_t)(rb * 128) * DIM;
    const __nv_bfloat16* pB = g_pbf + (size_t)(cb * 128) * DIM;

    float acc[4][4][4];
    #pragma unroll
    for (int mi = 0; mi < 4; mi++)
        #pragma unroll
        for (int ni = 0; ni < 4; ni++)
            #pragma unroll
            for (int r = 0; r < 4; r++) acc[mi][ni][r] = 0.f;

    // loader: 2048 x 16B transfers per 64-K stage (A 1024, B 1024), 8/thread
    auto load_chunk = [&](int stg, int kt) {
        uint32_t base = sbase + (uint32_t)stg * STG_B;
        #pragma unroll
        for (int i = 0; i < 8; i++) {
            int c = tid + (i << 8);
            int isB = (c >= 1024);
            int cc = c & 1023;
            int row = cc >> 3, seg = cc & 7;
            const __nv_bfloat16* gp = (isB ? pB : qB) + (size_t)row * DIM + kt + seg * 8;
            uint32_t d = base + (isB ? A_BYTES : 0u) + (uint32_t)row * ROW_B + ((uint32_t)seg << 4);
            cp16(d, gp);
        }
        CP_COMMIT();
    };

    auto compute_chunk = [&](int stg) {
        uint32_t aB = sbase + (uint32_t)stg * STG_B;
        uint32_t bB = aB + A_BYTES;
        #pragma unroll
        for (int ks = 0; ks < 4; ks++) {
            uint32_t af_[4][4];
            #pragma unroll
            for (int mi = 0; mi < 4; mi++) {
                uint32_t addr = aB
                    + (uint32_t)((warpM * 64 + mi * 16 + (lane & 15)) * ROW_B)
                    + (uint32_t)(ks * 32 + ((lane >> 4) << 4));
                LDSM4(af_[mi][0], af_[mi][1], af_[mi][2], af_[mi][3], addr);
            }
            uint32_t bf_[2][4];
            #pragma unroll
            for (int nj = 0; nj < 2; nj++) {
                uint32_t addr = bB
                    + (uint32_t)((warpN * 32 + nj * 16 + (lane & 7) + ((lane >> 4) << 3)) * ROW_B)
                    + (uint32_t)(ks * 32 + (((lane >> 3) & 1) << 4));
                LDSM4(bf_[nj][0], bf_[nj][1], bf_[nj][2], bf_[nj][3], addr);
            }
            #pragma unroll
            for (int mi = 0; mi < 4; mi++)
                #pragma unroll
                for (int ni = 0; ni < 4; ni++) {
                    uint32_t b0 = bf_[ni >> 1][(ni & 1) << 1];
                    uint32_t b1 = bf_[ni >> 1][((ni & 1) << 1) + 1];
                    MMA16816(acc[mi][ni], af_[mi][0], af_[mi][1], af_[mi][2], af_[mi][3], b0, b1);
                }
        }
    };

    // 2-stage pipeline over 12 x 64-K chunks (prefetch distance = 1 chunk)
    load_chunk(0, 0);
    for (int c = 0; c < NCH64; c++) {
        CP_WAIT0();                  // only chunk c is in flight here
        __syncthreads();
        if (c + 1 < NCH64) load_chunk((c + 1) & 1, (c + 1) * 64);
        compute_chunk(c & 1);
    }

    // ---- epilogue: block max, poly-exp sum, rank counts ----
    const int g = lane >> 2, q4 = lane & 3;
    #pragma unroll
    for (int mi = 0; mi < 4; mi++) {
        #pragma unroll
        for (int h = 0; h < 2; h++) {
            int row = rb * 128 + warpM * 64 + mi * 16 + h * 8 + g;
            float st = g_starget[row];
            int tcol = row * 8;
            float v[8];
            #pragma unroll
            for (int ni = 0; ni < 4; ni++) {
                v[ni * 2 + 0] = acc[mi][ni][h * 2 + 0];
                v[ni * 2 + 1] = acc[mi][ni][h * 2 + 1];
            }
            float mx = v[0];
            #pragma unroll
            for (int j = 1; j < 8; j++) mx = fmaxf(mx, v[j]);
            int cgt = 0, ceq = 0;
            #pragma unroll
            for (int j = 0; j < 8; j++) {
                int colg = cb * 128 + warpN * 32 + (j >> 1) * 8 + q4 * 2 + (j & 1);
                if (v[j] > st && colg != tcol) cgt++;
                if (v[j] == st && colg < tcol) ceq++;
            }
            int cnt = cgt | (ceq << 16);
            mx = fmaxf(mx, __shfl_xor_sync(0xffffffffu, mx, 1));
            mx = fmaxf(mx, __shfl_xor_sync(0xffffffffu, mx, 2));
            cnt += __shfl_xor_sync(0xffffffffu, cnt, 1);
            cnt += __shfl_xor_sync(0xffffffffu, cnt, 2);
            float s = 0.f;
            #pragma unroll
            for (int j = 0; j < 8; j++) s += fexp(v[j] - mx);
            s += __shfl_xor_sync(0xffffffffu, s, 1);
            s += __shfl_xor_sync(0xffffffffu, s, 2);
            if (q4 == 0) {
                int idx = row * NB32 + cb * 4 + warpN;
                g_smax[idx] = mx;
                g_ssum[idx] = s;
                g_cnt[idx]  = cnt;
            }
        }
    }
}

// ---------------------------------------------------------------------------
// Kernel 3: warp-per-row combine -> per-block partial -> last block writes out.
// grid = 256, block = 256 (8 rows per block).
// ---------------------------------------------------------------------------
__global__ __launch_bounds__(256)
void combine_kernel(float* __restrict__ out) {
    __shared__ float sh[8];
    const int lane = threadIdx.x & 31;
    const int warp = threadIdx.x >> 5;
    const int row = blockIdx.x * 8 + warp;

    const float4* smax4 = (const float4*)(g_smax + (size_t)row * NB32);
    const float4* ssum4 = (const float4*)(g_ssum + (size_t)row * NB32);
    const int4*   cnt4  = (const int4*)  (g_cnt  + (size_t)row * NB32);

    // pass 1: global row max + rank counts
    float mx = -3.0e38f;
    int cnt = 0;
    #pragma unroll
    for (int k = 0; k < 4; k++) {
        float4 m = smax4[k * 32 + lane];
        int4   c = cnt4 [k * 32 + lane];
        mx = fmaxf(fmaxf(fmaxf(mx, m.x), fmaxf(m.y, m.z)), m.w);
        cnt += c.x + c.y + c.z + c.w;
    }
    #pragma unroll
    for (int o = 16; o > 0; o >>= 1) {
        mx = fmaxf(mx, __shfl_xor_sync(0xffffffffu, mx, o));
        cnt += __shfl_xor_sync(0xffffffffu, cnt, o);
    }

    // pass 2: S = sum_b ssum_b * exp(smax_b - M)
    float S = 0.f;
    #pragma unroll
    for (int k = 0; k < 4; k++) {
        float4 m = smax4[k * 32 + lane];
        float4 s = ssum4[k * 32 + lane];
        S += s.x * fexp(m.x - mx) + s.y * fexp(m.y - mx)
           + s.z * fexp(m.z - mx) + s.w * fexp(m.w - mx);
    }
    #pragma unroll
    for (int o = 16; o > 0; o >>= 1) S += __shfl_xor_sync(0xffffffffu, S, o);

    if (lane == 0) {
        float rank = (float)((cnt & 0xffff) + (cnt >> 16));
        float raw = mx + logf(S) - g_starget[row];
        float dr = rank - OPT_RANK;
        float w = 1.0f + ALPHA_C * expf(-(dr * dr) / (2.0f * SIGMA_C * SIGMA_C));
        sh[warp] = raw * w;
    }
    __syncthreads();
    if (threadIdx.x == 0) {
        float t = 0.f;
        #pragma unroll
        for (int i = 0; i < 8; i++) t += sh[i];
        g_part[blockIdx.x] = t;
        __threadfence();
        unsigned int ticket = atomicAdd(&g_tick, 1u);
        if (ticket == 255u) {                  // last block: deterministic sum
            float tot = 0.f;
            for (int i = 0; i < 256; i++) tot += g_part[i];
            out[0] = tot * (1.0f / (float)BQ);
            g_tick = 0u;                       // reset for next replay
        }
    }
}

// ---------------------------------------------------------------------------
extern "C" void kernel_launch(void* const* d_in, const int* in_sizes, int n_in,
                              void* d_out, int out_size) {
    const float* q = (const float*)d_in[0];   // [2048, 768] fp32
    const float* p = (const float*)d_in[1];   // [16384, 768] fp32
    float* out = (float*)d_out;

    cudaFuncSetAttribute(score_kernel,
                         cudaFuncAttributeMaxDynamicSharedMemorySize, SMEM_BYTES);

    convert_q_kernel<<<(BQ * DIM) / 8 / 256, 256>>>(q);     // launch 1
    convert_p_kernel<<<(NPAS * DIM) / 8 / 256, 256>>>(p);   // launch 2
    target_kernel<<<BQ / 8, 256>>>(q, p);                   // launch 3
    dim3 grid(NPAS / 128, BQ / 128);                        // (128, 16)
    score_kernel<<<grid, 256, SMEM_BYTES>>>();              // launch 4 (ncu slot)
    combine_kernel<<<BQ / 8, 256>>>(out);                   // launch 5
}

// round 14
// speedup vs baseline: 1.2068x; 1.1054x over previous
#include <cuda_runtime.h>
#include <cuda_bf16.h>
#include <stdint.h>

// Problem constants
#define BQ 2048       // queries (rows)
#define DIM 768       // embedding dim
#define NPAS 16384    // passages (cols)
#define NB32 512      // 32-col partial blocks per row
#define ALPHA_C 2.6f
#define OPT_RANK 1.0f
#define SIGMA_C 1.8f

// Static device scratch (allocation-free)
__device__ __align__(16) __nv_bfloat16 g_qbf[BQ * DIM];
__device__ __align__(16) __nv_bfloat16 g_pbf[NPAS * DIM];
__device__ float g_starget[BQ];
__device__ __align__(16) float g_smax[BQ * NB32];
__device__ __align__(16) float g_ssum[BQ * NB32];
__device__ __align__(16) int   g_cnt[BQ * NB32];
__device__ float g_part[256];
__device__ unsigned int g_tick = 0;

// ---------------------------------------------------------------------------
// PTX helpers (plain sm_80+ PTX only; tcgen05 is ptxas-blocked on this build)
// ---------------------------------------------------------------------------
__device__ __forceinline__ uint32_t smem_u32(const void* p) {
    uint32_t a;
    asm("{ .reg .u64 t; cvta.to.shared.u64 t, %1; cvt.u32.u64 %0, t; }"
        : "=r"(a) : "l"(p));
    return a;
}
__device__ __forceinline__ void cp16(uint32_t dst, const void* src) {
    asm volatile("cp.async.cg.shared.global [%0], [%1], 16;"
                 :: "r"(dst), "l"(src) : "memory");
}
#define CP_COMMIT() asm volatile("cp.async.commit_group;" ::: "memory")
#define CP_WAIT0()  asm volatile("cp.async.wait_group 0;" ::: "memory")

#define LDSM4(r0, r1, r2, r3, addr) \
    asm volatile("ldmatrix.sync.aligned.m8n8.x4.shared.b16 {%0,%1,%2,%3}, [%4];" \
                 : "=r"(r0), "=r"(r1), "=r"(r2), "=r"(r3) : "r"(addr))

#define MMA16816(c, a0, a1, a2, a3, b0, b1) \
    asm volatile("mma.sync.aligned.m16n8k16.row.col.f32.bf16.bf16.f32 " \
                 "{%0,%1,%2,%3}, {%4,%5,%6,%7}, {%8,%9}, {%0,%1,%2,%3};" \
                 : "+f"((c)[0]), "+f"((c)[1]), "+f"((c)[2]), "+f"((c)[3]) \
                 : "r"(a0), "r"(a1), "r"(a2), "r"(a3), "r"(b0), "r"(b1))

// MUFU-free e^x for x <= 0 (FMA-pipe only; rel err < 3e-6)
__device__ __forceinline__ float fexp(float x) {
    float t = x * 1.44269504088896f;               // log2(e) * x
    float z = t + 12582912.0f;                     // 2^23 * 1.5 magic (RN)
    int   n = __float_as_int(z) - 0x4B400000;      // nearest int
    float f = t - (float)n;                        // f in [-0.5, 0.5]
    float r = 0.0013333558f;                       // 2^f Taylor (ln2^k/k!)
    r = fmaf(r, f, 0.0096181291f);
    r = fmaf(r, f, 0.0555041087f);
    r = fmaf(r, f, 0.2402265070f);
    r = fmaf(r, f, 0.6931471806f);
    r = fmaf(r, f, 1.0f);
    r = __int_as_float(__float_as_int(r) + (n << 23));
    return (x > -87.0f) ? r : 0.0f;                // avoid exponent wrap
}

// ---------------------------------------------------------------------------
// Kernels 0a/0b: fp32 -> bf16 conversion (8 elems / thread), q and p split
// (split keeps score_kernel in the ncu capture slot = launch #4)
// ---------------------------------------------------------------------------
__global__ void convert_q_kernel(const float* __restrict__ q) {
    size_t i = ((size_t)blockIdx.x * blockDim.x + threadIdx.x) * 8;
    float4 a = *(const float4*)(q + i);
    float4 b = *(const float4*)(q + i + 4);
    __nv_bfloat162 v0 = __floats2bfloat162_rn(a.x, a.y);
    __nv_bfloat162 v1 = __floats2bfloat162_rn(a.z, a.w);
    __nv_bfloat162 v2 = __floats2bfloat162_rn(b.x, b.y);
    __nv_bfloat162 v3 = __floats2bfloat162_rn(b.z, b.w);
    uint4 u;
    u.x = *(uint32_t*)&v0; u.y = *(uint32_t*)&v1;
    u.z = *(uint32_t*)&v2; u.w = *(uint32_t*)&v3;
    *(uint4*)(g_qbf + i) = u;
}
__global__ void convert_p_kernel(const float* __restrict__ p) {
    size_t i = ((size_t)blockIdx.x * blockDim.x + threadIdx.x) * 8;
    float4 a = *(const float4*)(p + i);
    float4 b = *(const float4*)(p + i + 4);
    __nv_bfloat162 v0 = __floats2bfloat162_rn(a.x, a.y);
    __nv_bfloat162 v1 = __floats2bfloat162_rn(a.z, a.w);
    __nv_bfloat162 v2 = __floats2bfloat162_rn(b.x, b.y);
    __nv_bfloat162 v3 = __floats2bfloat162_rn(b.z, b.w);
    uint4 u;
    u.x = *(uint32_t*)&v0; u.y = *(uint32_t*)&v1;
    u.z = *(uint32_t*)&v2; u.w = *(uint32_t*)&v3;
    *(uint4*)(g_pbf + i) = u;
}

// ---------------------------------------------------------------------------
// Kernel 1: exact fp32 s_target[i] = dot(q[i], p[8i])   (one warp per row)
// ---------------------------------------------------------------------------
__global__ void target_kernel(const float* __restrict__ q,
                              const float* __restrict__ p) {
    int w = (blockIdx.x * blockDim.x + threadIdx.x) >> 5;
    int lane = threadIdx.x & 31;
    if (w >= BQ) return;
    const float* qr = q + (size_t)w * DIM;
    const float* pr = p + (size_t)(w * 8) * DIM;
    float s = 0.f;
    #pragma unroll 4
    for (int k = lane; k < DIM; k += 32) s = fmaf(qr[k], pr[k], s);
    #pragma unroll
    for (int o = 16; o > 0; o >>= 1) s += __shfl_down_sync(0xffffffffu, s, o);
    if (lane == 0) g_starget[w] = s;
}

// ---------------------------------------------------------------------------
// Kernel 2: 128x128 score tile per CTA via mma.sync bf16 (HMMA path).
// BK=64 chunks, 2-stage cp.async ring. De-phase-locked mainloop:
//  - each warp walks ks in order (wid+i)&3  -> warps spread across LDSM/MMA
//    phases, keeping tensor AND smem pipes simultaneously fed
//  - cp.async prefetch spread across the 4 ks iterations (2 per thread each)
// Epilogue: per-(row, 32col) block max, poly-exp partial sum, rank counts.
// grid = (128, 16), 256 threads.
// ---------------------------------------------------------------------------
#define ROW_B 144u
#define A_BYTES (128u * ROW_B)          // 18432
#define STG_B (2u * A_BYTES)            // 36864 (A + B)
#define SMEM_BYTES (2u * STG_B)         // 73728
#define NCH64 12                        // 768 / 64

__global__ __launch_bounds__(256, 2)
void score_kernel() {
    extern __shared__ char smem[];
    const uint32_t sbase = smem_u32(smem);
    const int tid = threadIdx.x;
    const int lane = tid & 31;
    const int wid = tid >> 5;
    const int warpM = wid & 1;      // 2 warps along M (64 rows each)
    const int warpN = wid >> 1;     // 4 warps along N (32 cols each)
    const int cb = blockIdx.x;      // column block 0..127
    const int rb = blockIdx.y;      // row block 0..15

    const __nv_bfloat16* qB = g_qbf + (size_t)(rb * 128) * DIM;
    const __nv_bfloat16* pB = g_pbf + (size_t)(cb * 128) * DIM;

    // Precomputed LDSM base offsets (relative to stage base)
    const uint32_t aoff = (uint32_t)((warpM * 64 + (lane & 15)) * ROW_B)
                        + (uint32_t)((lane >> 4) << 4);
    const uint32_t boff = A_BYTES
                        + (uint32_t)((warpN * 32 + (lane & 7) + ((lane >> 4) << 3)) * ROW_B)
                        + (uint32_t)(((lane >> 3) & 1) << 4);

    // Precomputed loader slot (this thread's 8 transfers: i-th iter, t in {0,1})
    // cc2 = tid + t*256 + i*512 ; isB = cc2 >= 1024
    float acc[4][4][4];
    #pragma unroll
    for (int mi = 0; mi < 4; mi++)
        #pragma unroll
        for (int ni = 0; ni < 4; ni++)
            #pragma unroll
            for (int r = 0; r < 4; r++) acc[mi][ni][r] = 0.f;

    // full prefetch of chunk 0
    {
        #pragma unroll
        for (int i = 0; i < 8; i++) {
            int c = tid + (i << 8);
            int isB = (c >= 1024);
            int cc = c & 1023;
            int row = cc >> 3, seg = cc & 7;
            const __nv_bfloat16* gp = (isB ? pB : qB) + (size_t)row * DIM + seg * 8;
            uint32_t d = sbase + (isB ? A_BYTES : 0u) + (uint32_t)row * ROW_B + ((uint32_t)seg << 4);
            cp16(d, gp);
        }
        CP_COMMIT();
    }

    for (int c = 0; c < NCH64; c++) {
        CP_WAIT0();
        __syncthreads();
        const uint32_t cur = sbase + (uint32_t)(c & 1) * STG_B;
        const uint32_t nxt = sbase + (uint32_t)((c + 1) & 1) * STG_B;
        const int nkt = (c + 1) * 64;
        const bool pf = (c + 1 < NCH64);

        #pragma unroll
        for (int i = 0; i < 4; i++) {
            // spread prefetch: 2 cp16 per thread per ks iteration
            if (pf) {
                #pragma unroll
                for (int t = 0; t < 2; t++) {
                    int cc2 = tid + (t << 8) + (i << 9);
                    int isB = (cc2 >= 1024);
                    int cc = cc2 & 1023;
                    int row = cc >> 3, seg = cc & 7;
                    const __nv_bfloat16* gp =
                        (isB ? pB : qB) + (size_t)row * DIM + nkt + seg * 8;
                    uint32_t d = nxt + (isB ? A_BYTES : 0u)
                               + (uint32_t)row * ROW_B + ((uint32_t)seg << 4);
                    cp16(d, gp);
                }
            }
            // staggered ks: warps spread across the 4 K-phases
            const int ks = (wid + i) & 3;
            const uint32_t kso = (uint32_t)(ks << 5);   // ks * 32 bytes
            uint32_t af_[4][4];
            #pragma unroll
            for (int mi = 0; mi < 4; mi++) {
                LDSM4(af_[mi][0], af_[mi][1], af_[mi][2], af_[mi][3],
                      cur + aoff + (uint32_t)(mi * 16) * ROW_B + kso);
            }
            uint32_t bf_[2][4];
            #pragma unroll
            for (int nj = 0; nj < 2; nj++) {
                LDSM4(bf_[nj][0], bf_[nj][1], bf_[nj][2], bf_[nj][3],
                      cur + boff + (uint32_t)(nj * 16) * ROW_B + kso);
            }
            #pragma unroll
            for (int mi = 0; mi < 4; mi++)
                #pragma unroll
                for (int ni = 0; ni < 4; ni++) {
                    uint32_t b0 = bf_[ni >> 1][(ni & 1) << 1];
                    uint32_t b1 = bf_[ni >> 1][((ni & 1) << 1) + 1];
                    MMA16816(acc[mi][ni], af_[mi][0], af_[mi][1], af_[mi][2], af_[mi][3], b0, b1);
                }
        }
        if (pf) CP_COMMIT();
    }

    // ---- epilogue: block max, poly-exp sum, rank counts ----
    const int g = lane >> 2, q4 = lane & 3;
    #pragma unroll
    for (int mi = 0; mi < 4; mi++) {
        #pragma unroll
        for (int h = 0; h < 2; h++) {
            int row = rb * 128 + warpM * 64 + mi * 16 + h * 8 + g;
            float st = g_starget[row];
            int tcol = row * 8;
            float v[8];
            #pragma unroll
            for (int ni = 0; ni < 4; ni++) {
                v[ni * 2 + 0] = acc[mi][ni][h * 2 + 0];
                v[ni * 2 + 1] = acc[mi][ni][h * 2 + 1];
            }
            float mx = v[0];
            #pragma unroll
            for (int j = 1; j < 8; j++) mx = fmaxf(mx, v[j]);
            int cgt = 0, ceq = 0;
            #pragma unroll
            for (int j = 0; j < 8; j++) {
                int colg = cb * 128 + warpN * 32 + (j >> 1) * 8 + q4 * 2 + (j & 1);
                if (v[j] > st && colg != tcol) cgt++;
                if (v[j] == st && colg < tcol) ceq++;
            }
            int cnt = cgt | (ceq << 16);
            mx = fmaxf(mx, __shfl_xor_sync(0xffffffffu, mx, 1));
            mx = fmaxf(mx, __shfl_xor_sync(0xffffffffu, mx, 2));
            cnt += __shfl_xor_sync(0xffffffffu, cnt, 1);
            cnt += __shfl_xor_sync(0xffffffffu, cnt, 2);
            float s = 0.f;
            #pragma unroll
            for (int j = 0; j < 8; j++) s += fexp(v[j] - mx);
            s += __shfl_xor_sync(0xffffffffu, s, 1);
            s += __shfl_xor_sync(0xffffffffu, s, 2);
            if (q4 == 0) {
                int idx = row * NB32 + cb * 4 + warpN;
                g_smax[idx] = mx;
                g_ssum[idx] = s;
                g_cnt[idx]  = cnt;
            }
        }
    }
}

// ---------------------------------------------------------------------------
// Kernel 3: warp-per-row combine -> per-block partial -> last block writes out.
// grid = 256, block = 256 (8 rows per block).
// ---------------------------------------------------------------------------
__global__ __launch_bounds__(256)
void combine_kernel(float* __restrict__ out) {
    __shared__ float sh[8];
    const int lane = threadIdx.x & 31;
    const int warp = threadIdx.x >> 5;
    const int row = blockIdx.x * 8 + warp;

    const float4* smax4 = (const float4*)(g_smax + (size_t)row * NB32);
    const float4* ssum4 = (const float4*)(g_ssum + (size_t)row * NB32);
    const int4*   cnt4  = (const int4*)  (g_cnt  + (size_t)row * NB32);

    // pass 1: global row max + rank counts
    float mx = -3.0e38f;
    int cnt = 0;
    #pragma unroll
    for (int k = 0; k < 4; k++) {
        float4 m = smax4[k * 32 + lane];
        int4   c = cnt4 [k * 32 + lane];
        mx = fmaxf(fmaxf(fmaxf(mx, m.x), fmaxf(m.y, m.z)), m.w);
        cnt += c.x + c.y + c.z + c.w;
    }
    #pragma unroll
    for (int o = 16; o > 0; o >>= 1) {
        mx = fmaxf(mx, __shfl_xor_sync(0xffffffffu, mx, o));
        cnt += __shfl_xor_sync(0xffffffffu, cnt, o);
    }

    // pass 2: S = sum_b ssum_b * exp(smax_b - M)
    float S = 0.f;
    #pragma unroll
    for (int k = 0; k < 4; k++) {
        float4 m = smax4[k * 32 + lane];
        float4 s = ssum4[k * 32 + lane];
        S += s.x * fexp(m.x - mx) + s.y * fexp(m.y - mx)
           + s.z * fexp(m.z - mx) + s.w * fexp(m.w - mx);
    }
    #pragma unroll
    for (int o = 16; o > 0; o >>= 1) S += __shfl_xor_sync(0xffffffffu, S, o);

    if (lane == 0) {
        float rank = (float)((cnt & 0xffff) + (cnt >> 16));
        float raw = mx + logf(S) - g_starget[row];
        float dr = rank - OPT_RANK;
        float w = 1.0f + ALPHA_C * expf(-(dr * dr) / (2.0f * SIGMA_C * SIGMA_C));
        sh[warp] = raw * w;
    }
    __syncthreads();
    if (threadIdx.x == 0) {
        float t = 0.f;
        #pragma unroll
        for (int i = 0; i < 8; i++) t += sh[i];
        g_part[blockIdx.x] = t;
        __threadfence();
        unsigned int ticket = atomicAdd(&g_tick, 1u);
        if (ticket == 255u) {                  // last block: deterministic sum
            float tot = 0.f;
            for (int i = 0; i < 256; i++) tot += g_part[i];
            out[0] = tot * (1.0f / (float)BQ);
            g_tick = 0u;                       // reset for next replay
        }
    }
}

// ---------------------------------------------------------------------------
extern "C" void kernel_launch(void* const* d_in, const int* in_sizes, int n_in,
                              void* d_out, int out_size) {
    const float* q = (const float*)d_in[0];   // [2048, 768] fp32
    const float* p = (const float*)d_in[1];   // [16384, 768] fp32
    float* out = (float*)d_out;

    cudaFuncSetAttribute(score_kernel,
                         cudaFuncAttributeMaxDynamicSharedMemorySize, SMEM_BYTES);

    convert_q_kernel<<<(BQ * DIM) / 8 / 256, 256>>>(q);     // launch 1
    convert_p_kernel<<<(NPAS * DIM) / 8 / 256, 256>>>(p);   // launch 2
    target_kernel<<<BQ / 8, 256>>>(q, p);                   // launch 3
    dim3 grid(NPAS / 128, BQ / 128);                        // (128, 16)
    score_kernel<<<grid, 256, SMEM_BYTES>>>();              // launch 4 (ncu slot)
    combine_kernel<<<BQ / 8, 256>>>(out);                   // launch 5
}